// round 3
// baseline (speedup 1.0000x reference)
#include <cuda_runtime.h>
#include <math.h>

#define Dn 384
#define Nn 96
#define FULLMASK 0xffffffffu

// Shared memory layout (dynamic): P matrix + per-step scratch.
struct Smem {
    float P[Dn * Nn];     // eigfunc[:, :96], row-major [site][component]
    float probs[Dn];      // window probs (scan)
    float cdfa[Dn];       // window running cdf (scan)
    float w[Nn];          // w = C v broadcast
    int   cnt[32];        // per-warp counts for position selection
    float q_s;
    float inv_s;
    int   pos_s;
    float cond_s;
};

__global__ void __launch_bounds__(1024, 1)
sds_kernel(const float* __restrict__ eig, const float* __restrict__ u,
           float* __restrict__ out)
{
    extern __shared__ unsigned char smraw[];
    Smem* sm = reinterpret_cast<Smem*>(smraw);
    const int tid = threadIdx.x;
    const int wi  = tid >> 5;   // warp id  -> row group (rows 3*wi..3*wi+2)
    const int lj  = tid & 31;   // lane id  -> col group (cols 3*lj..3*lj+2)

    // Load P = eigfunc[:, :96] into smem. Row r contiguous (first 96 of 384).
    for (int r = wi; r < Dn; r += 32) {
#pragma unroll
        for (int b = 0; b < 3; b++)
            sm->P[r * Nn + lj * 3 + b] = eig[r * Dn + lj * 3 + b];
    }

    // Committed conditional-kernel factor C (96x96) = I, 3x3 tile per thread.
    float cb[3][3];
#pragma unroll
    for (int a = 0; a < 3; a++)
#pragma unroll
        for (int b = 0; b < 3; b++)
            cb[a][b] = (3 * wi + a == 3 * lj + b) ? 1.0f : 0.0f;

    __syncthreads();

    int prev = -1;
    for (int k = 0; k < Nn; k++) {
        const int xmin = prev + 1;
        const int xmax = Dn - Nn + k + 1;   // exclusive

        // Working copy for the speculative scan.
        float cw[3][3];
#pragma unroll
        for (int a = 0; a < 3; a++)
#pragma unroll
            for (int b = 0; b < 3; b++)
                cw[a][b] = cb[a][b];

        float run = 1.0f;   // running prod of pivots (1-q), replicated
        float cdf = 0.0f;   // running cdf, replicated
        int jend = xmax;

        // ---- speculative scan: condition-empty sweep ----
        for (int j = xmin; j < xmax; j++) {
            const float* vp = &sm->P[j * Nn + 3 * lj];
            const float v0 = vp[0], v1 = vp[1], v2 = vp[2];
            // partial matvec w = C v for this thread's 3 rows / 3 cols
            float p0 = cw[0][0]*v0 + cw[0][1]*v1 + cw[0][2]*v2;
            float p1 = cw[1][0]*v0 + cw[1][1]*v1 + cw[1][2]*v2;
            float p2 = cw[2][0]*v0 + cw[2][1]*v1 + cw[2][2]*v2;
#pragma unroll
            for (int off = 16; off > 0; off >>= 1) {
                p0 += __shfl_xor_sync(FULLMASK, p0, off);
                p1 += __shfl_xor_sync(FULLMASK, p1, off);
                p2 += __shfl_xor_sync(FULLMASK, p2, off);
            }
            if (lj == 0) {
                sm->w[3*wi+0] = p0; sm->w[3*wi+1] = p1; sm->w[3*wi+2] = p2;
            }
            __syncthreads();
            const float wc0 = sm->w[3*lj+0];
            const float wc1 = sm->w[3*lj+1];
            const float wc2 = sm->w[3*lj+2];
            if (wi == 0) {
                // q = v . w  (lane lj owns components 3lj..3lj+2)
                float qp = v0*wc0 + v1*wc1 + v2*wc2;
#pragma unroll
                for (int off = 16; off > 0; off >>= 1)
                    qp += __shfl_xor_sync(FULLMASK, qp, off);
                if (lj == 0) {
                    const float q   = qp;
                    const float piv = 1.0f - q;            // LU pivot
                    const float inv = (fabsf(piv) > 1e-30f) ? __frcp_rn(piv) : 0.0f;
                    sm->q_s   = q;
                    sm->inv_s = inv;
                    float prob = run * q;                   // cp_excl * (1-piv)
                    if (!(fabsf(prob) > 1e-15f)) prob = 0.0f;
                    sm->probs[j] = prob;
                    sm->cdfa[j]  = cdf + prob;
                }
            }
            __syncthreads();
            const float q  = sm->q_s;
            const float iv = sm->inv_s;
            // rank-1 update: C += w w^T / (1-q)
            const float t0 = p0 * iv, t1 = p1 * iv, t2 = p2 * iv;
            cw[0][0] += t0*wc0; cw[0][1] += t0*wc1; cw[0][2] += t0*wc2;
            cw[1][0] += t1*wc0; cw[1][1] += t1*wc1; cw[1][2] += t1*wc2;
            cw[2][0] += t2*wc0; cw[2][1] += t2*wc1; cw[2][2] += t2*wc2;
            // replicated scalar bookkeeping (identical in every thread)
            float prob = run * q;
            if (!(fabsf(prob) > 1e-15f)) prob = 0.0f;
            cdf += prob;
            run *= (1.0f - q);
            // Remaining window mass is bounded by |run|; once negligible the
            // CDF crossing is already determined (total == 1 exactly in exact
            // arithmetic; truncation error ~1e-12 << fp32 noise).
            if (fabsf(run) < 1e-12f * cdf) { jend = j + 1; break; }
        }
        __syncthreads();

        // ---- position selection: pos = xmin + #{ cdf[j] < u*total } ----
        const float thr = u[k] * cdf;       // cdf == total over (effective) window
        const int len = jend - xmin;        // <= 289 < 1024: one element/thread
        int pred = 0;
        if (tid < len) pred = (sm->cdfa[xmin + tid] < thr) ? 1 : 0;
        const unsigned bal = __ballot_sync(FULLMASK, pred);
        if (lj == 0) sm->cnt[wi] = __popc(bal);
        __syncthreads();
        if (wi == 0) {
            int c = sm->cnt[lj];
#pragma unroll
            for (int off = 16; off > 0; off >>= 1)
                c += __shfl_xor_sync(FULLMASK, c, off);
            if (lj == 0) {
                int pos = xmin + c;
                const int pmax = (xmax < jend ? xmax : jend) - 1;
                if (pos > pmax) pos = pmax;
                sm->pos_s  = pos;
                sm->cond_s = sm->probs[pos];
            }
        }
        __syncthreads();
        const int pos = sm->pos_s;

        // ---- commit: replay empties xmin..pos-1, occupy pos, onto cb ----
        for (int j = xmin; j <= pos; j++) {
            const float* vp = &sm->P[j * Nn + 3 * lj];
            const float v0 = vp[0], v1 = vp[1], v2 = vp[2];
            float p0 = cb[0][0]*v0 + cb[0][1]*v1 + cb[0][2]*v2;
            float p1 = cb[1][0]*v0 + cb[1][1]*v1 + cb[1][2]*v2;
            float p2 = cb[2][0]*v0 + cb[2][1]*v1 + cb[2][2]*v2;
#pragma unroll
            for (int off = 16; off > 0; off >>= 1) {
                p0 += __shfl_xor_sync(FULLMASK, p0, off);
                p1 += __shfl_xor_sync(FULLMASK, p1, off);
                p2 += __shfl_xor_sync(FULLMASK, p2, off);
            }
            if (lj == 0) {
                sm->w[3*wi+0] = p0; sm->w[3*wi+1] = p1; sm->w[3*wi+2] = p2;
            }
            __syncthreads();
            const float wc0 = sm->w[3*lj+0];
            const float wc1 = sm->w[3*lj+1];
            const float wc2 = sm->w[3*lj+2];
            if (wi == 0) {
                float qp = v0*wc0 + v1*wc1 + v2*wc2;
#pragma unroll
                for (int off = 16; off > 0; off >>= 1)
                    qp += __shfl_xor_sync(FULLMASK, qp, off);
                if (lj == 0) {
                    const float q = qp;
                    float inv;
                    if (j < pos) {                      // condition empty
                        const float piv = 1.0f - q;
                        inv = (fabsf(piv) > 1e-30f) ? __frcp_rn(piv) : 0.0f;
                    } else {                            // condition occupied
                        inv = (fabsf(q) > 1e-30f) ? (-__frcp_rn(q)) : 0.0f;
                    }
                    sm->inv_s = inv;
                }
            }
            __syncthreads();
            const float iv = sm->inv_s;
            const float t0 = p0 * iv, t1 = p1 * iv, t2 = p2 * iv;
            cb[0][0] += t0*wc0; cb[0][1] += t0*wc1; cb[0][2] += t0*wc2;
            cb[1][0] += t1*wc0; cb[1][1] += t1*wc1; cb[1][2] += t1*wc2;
            cb[2][0] += t2*wc0; cb[2][1] += t2*wc1; cb[2][2] += t2*wc2;
        }

        if (tid == 0) {
            out[k]      = (float)pos;      // positions, then cond_probs
            out[Nn + k] = sm->cond_s;
        }
        prev = pos;
        __syncthreads();
    }
}

extern "C" void kernel_launch(void* const* d_in, const int* in_sizes, int n_in,
                              void* d_out, int out_size)
{
    (void)in_sizes; (void)n_in; (void)out_size;
    const float* eig = (const float*)d_in[0];   // eigfunc (384,384) f32
    const float* uu  = (const float*)d_in[1];   // u (96,) f32
    float* out = (float*)d_out;                 // [positions(96); cond_probs(96)]

    cudaFuncSetAttribute(sds_kernel,
                         cudaFuncAttributeMaxDynamicSharedMemorySize,
                         (int)sizeof(Smem));
    sds_kernel<<<1, 1024, sizeof(Smem)>>>(eig, uu, out);
}

// round 5
// speedup vs baseline: 1.9770x; 1.9770x over previous
#include <cuda_runtime.h>
#include <math.h>

#define Dn 384
#define Nn 96
#define TPB 256
#define FULLMASK 0xffffffffu

// Shared memory layout (dynamic).
struct Smem {
    float P[Dn * Nn];      // eigfunc[:, :96], row-major [site][component]
    float probs[Dn];       // window probs (scan)
    float cdfa[Dn];        // window running cdf (scan)
    float w[2][Nn];        // w = C v broadcast (double-buffered by site parity)
    int   cnt[8];          // per-warp counts for position selection
};

// One site update on the factored conditional kernel K = P C P^T:
//   w = C v,  q = v^T w  (v = P[j, :96])
//   occupied=false: C += w w^T / (1-q)   (LU pivot = 1-q, guard |piv|>1e-30)
//   occupied=true : C -= w w^T / q       (guard |q|>1e-30)
// Tiling: 256 threads, thread owns C[6rt..6rt+6)[6ct..6ct+6),
//   rt = tid>>4 (16 row-tiles), ct = tid&15 (16 col-tiles).
// Row-reduce: 4-level butterfly over the 16 lanes sharing a row-tile
// (offsets 1,2,4,8 stay within each 16-lane half of the warp).
// Returns q, bitwise identical in every thread. ONE __syncthreads inside.
__device__ __forceinline__ float site_step(Smem* __restrict__ sm,
                                           float C[6][6],
                                           int j, int buf,
                                           int rt, int ct, int lane,
                                           bool occupied)
{
    const float* vp = &sm->P[j * Nn + 6 * ct];
    float v[6];
#pragma unroll
    for (int b = 0; b < 6; b++) v[b] = vp[b];

    // partial matvec over this thread's 6 cols
    float p[6];
#pragma unroll
    for (int a = 0; a < 6; a++) {
        float s = C[a][0] * v[0];
        s += C[a][1] * v[1];
        s += C[a][2] * v[2];
        s += C[a][3] * v[3];
        s += C[a][4] * v[4];
        s += C[a][5] * v[5];
        p[a] = s;
    }
    // 4-level butterfly over 16 col-tiles -> p[a] = w[6rt+a] in all 16 lanes
#pragma unroll
    for (int off = 1; off < 16; off <<= 1) {
#pragma unroll
        for (int a = 0; a < 6; a++)
            p[a] += __shfl_xor_sync(FULLMASK, p[a], off);
    }
    const int m = lane & 15;
    if (m < 6) sm->w[buf][6 * rt + m] = p[m];
    __syncthreads();

    // column-side w values (broadcast: lanes with same ct hit same address)
    float wc[6];
    const float* wp = &sm->w[buf][6 * ct];
#pragma unroll
    for (int b = 0; b < 6; b++) wc[b] = wp[b];

    // q = v . w : per-thread partial over its 6 cols, butterfly over 16 cts.
    float qp = v[0]*wc[0] + v[1]*wc[1] + v[2]*wc[2]
             + v[3]*wc[3] + v[4]*wc[4] + v[5]*wc[5];
#pragma unroll
    for (int off = 1; off < 16; off <<= 1)
        qp += __shfl_xor_sync(FULLMASK, qp, off);
    const float q = qp;

    float inv;
    if (!occupied) {
        const float piv = 1.0f - q;
        inv = (fabsf(piv) > 1e-30f) ? __frcp_rn(piv) : 0.0f;
    } else {
        inv = (fabsf(q) > 1e-30f) ? (-__frcp_rn(q)) : 0.0f;
    }

    // rank-1 update: C += inv * w_rows w_cols^T
#pragma unroll
    for (int a = 0; a < 6; a++) {
        const float t = p[a] * inv;
#pragma unroll
        for (int b = 0; b < 6; b++)
            C[a][b] += t * wc[b];
    }
    return q;
}

__global__ void __launch_bounds__(TPB, 1)
sds_kernel(const float* __restrict__ eig, const float* __restrict__ u,
           float* __restrict__ out)
{
    extern __shared__ unsigned char smraw[];
    Smem* sm = reinterpret_cast<Smem*>(smraw);
    const int tid  = threadIdx.x;
    const int lane = tid & 31;
    const int warp = tid >> 5;
    const int rt   = tid >> 4;   // row-tile  (rows 6rt..6rt+5)
    const int ct   = tid & 15;   // col-tile  (cols 6ct..6ct+5)

    // Load P = eigfunc[:, :96] into smem (first 96 of each 384-row).
    for (int idx = tid; idx < Dn * Nn; idx += TPB) {
        const int r = idx / Nn, c = idx - r * Nn;
        sm->P[idx] = eig[r * Dn + c];
    }

    // Committed conditional-kernel factor C (96x96) = I, 6x6 tile per thread.
    float cb[6][6];
#pragma unroll
    for (int a = 0; a < 6; a++)
#pragma unroll
        for (int b = 0; b < 6; b++)
            cb[a][b] = (6 * rt + a == 6 * ct + b) ? 1.0f : 0.0f;

    __syncthreads();

    int prev = -1;
    int buf = 0;                 // w parity, toggled every site_step
    for (int k = 0; k < Nn; k++) {
        const int xmin = prev + 1;
        const int xmax = Dn - Nn + k + 1;   // exclusive
        const float uk = u[k];

        // Working copy for the speculative scan.
        float cw[6][6];
#pragma unroll
        for (int a = 0; a < 6; a++)
#pragma unroll
            for (int b = 0; b < 6; b++)
                cw[a][b] = cb[a][b];

        float run = 1.0f;   // running prod of pivots (1-q), replicated
        float cdf = 0.0f;   // running cdf, replicated
        int jend = xmax;

        // ---- speculative scan: condition-empty sweep ----
        for (int j = xmin; j < xmax; j++) {
            const float q = site_step(sm, cw, j, buf, rt, ct, lane, false);
            buf ^= 1;
            // replicated scalar bookkeeping (bitwise identical in all threads)
            float prob = run * q;               // cp_excl * (1 - piv)
            if (!(fabsf(prob) > 1e-15f)) prob = 0.0f;
            cdf += prob;
            if (tid == 0) { sm->probs[j] = prob; sm->cdfa[j] = cdf; }
            run *= (1.0f - q);
            // Remaining window mass <= |run|. Truncating at 3e-9*cdf is ~100x
            // below the fp32 noise already present in cdf.
            if (fabsf(run) < 3e-9f * cdf) { jend = j + 1; break; }
        }
        __syncthreads();   // tid0's probs/cdfa visible to all

        // ---- position selection: pos = xmin + #{ cdf[j] < u*total } ----
        const float thr = uk * cdf;         // cdf == total over effective window
        const int len = jend - xmin;        // <= 289: up to 2 elems/thread
        int cnt_t = 0;
        if (tid < len       && sm->cdfa[xmin + tid]       < thr) cnt_t++;
        if (tid + TPB < len && sm->cdfa[xmin + tid + TPB] < thr) cnt_t++;
        const int wsum = __reduce_add_sync(FULLMASK, cnt_t);
        if (lane == 0) sm->cnt[warp] = wsum;
        __syncthreads();
        int c = 0;
#pragma unroll
        for (int i = 0; i < 8; i++) c += sm->cnt[i];
        int pos = xmin + c;
        const int pmax = (xmax < jend ? xmax : jend) - 1;
        if (pos > pmax) pos = pmax;

        // ---- commit: replay empties xmin..pos-1, occupy pos, onto cb ----
        // (loop body contains a __syncthreads, so cdfa reads above are safely
        //  ordered before next step's scan overwrites)
        for (int j = xmin; j <= pos; j++) {
            site_step(sm, cb, j, buf, rt, ct, lane, j == pos);
            buf ^= 1;
        }

        if (tid == 0) {
            out[k]      = (float)pos;       // positions, then cond_probs
            out[Nn + k] = sm->probs[pos];
        }
        prev = pos;
    }
}

extern "C" void kernel_launch(void* const* d_in, const int* in_sizes, int n_in,
                              void* d_out, int out_size)
{
    (void)in_sizes; (void)n_in; (void)out_size;
    const float* eig = (const float*)d_in[0];   // eigfunc (384,384) f32
    const float* uu  = (const float*)d_in[1];   // u (96,) f32
    float* out = (float*)d_out;                 // [positions(96); cond_probs(96)]

    cudaFuncSetAttribute(sds_kernel,
                         cudaFuncAttributeMaxDynamicSharedMemorySize,
                         (int)sizeof(Smem));
    sds_kernel<<<1, TPB, sizeof(Smem)>>>(eig, uu, out);
}

// round 6
// speedup vs baseline: 3.9740x; 2.0102x over previous
#include <cuda_runtime.h>
#include <math.h>

#define Dn 384
#define Nn 96
#define TPB 256
#define WHIST 48
#define FULLMASK 0xffffffffu

// Dynamic shared memory layout (~170 KB).
struct Smem {
    float P[Dn * Nn];              // eigfunc[:, :96], row-major [site][component]
    float probs[Dn];               // window probs
    float cdfa[Dn];                // window running cdf
    float w[2][Nn];                // w = C v broadcast (double-buffered)
    __align__(16) float qp[2][16]; // per-rowgroup q partials (double-buffered)
    float whist[WHIST][Nn];        // per-site w history (for cheap commit)
    float invh[WHIST];             // per-site empty-conditioning inverse
    float qh[WHIST];               // per-site q
    int   cnt[8];                  // per-warp counts for position selection
};

// Sum of 16 floats from 16B-aligned smem; identical (deterministic) in all threads.
__device__ __forceinline__ float sum16(const float* q) {
    const float4* q4 = reinterpret_cast<const float4*>(q);
    float4 a = q4[0], b = q4[1], c = q4[2], d = q4[3];
    float s0 = (a.x + a.y) + (a.z + a.w);
    float s1 = (b.x + b.y) + (b.z + b.w);
    float s2 = (c.x + c.y) + (c.z + c.w);
    float s3 = (d.x + d.y) + (d.z + d.w);
    return (s0 + s1) + (s2 + s3);
}

// Produce phase for site j: p = (C v_j) reduced to full w-row values for this
// thread's 6 rows; write w rows + q partial to buffer `buf`.
// Tiling: rt = tid>>4 (rows 6rt..6rt+5), ct = tid&15 (cols 6ct..6ct+5).
// Butterfly offsets 1,2,4,8 stay within each 16-lane half-warp (same rt).
__device__ __forceinline__ void produce_site(Smem* __restrict__ sm,
                                             const float C[6][6], float p[6],
                                             int j, int buf, int rt, int ct)
{
    const float* vp = &sm->P[j * Nn + 6 * ct];
    float v0 = vp[0], v1 = vp[1], v2 = vp[2], v3 = vp[3], v4 = vp[4], v5 = vp[5];
#pragma unroll
    for (int a = 0; a < 6; a++) {
        float s = C[a][0] * v0;
        s += C[a][1] * v1;  s += C[a][2] * v2;
        s += C[a][3] * v3;  s += C[a][4] * v4;
        s += C[a][5] * v5;
        p[a] = s;
    }
#pragma unroll
    for (int off = 1; off < 16; off <<= 1) {
#pragma unroll
        for (int a = 0; a < 6; a++)
            p[a] += __shfl_xor_sync(FULLMASK, p[a], off);
    }
    // q partial over this warp-half's 6 rows (identical across the 16 lanes)
    const float* vr = &sm->P[j * Nn + 6 * rt];
    float qpart = vr[0]*p[0] + vr[1]*p[1] + vr[2]*p[2]
                + vr[3]*p[3] + vr[4]*p[4] + vr[5]*p[5];
    if (ct == 0) {
#pragma unroll
        for (int a = 0; a < 6; a++) sm->w[buf][6 * rt + a] = p[a];
        sm->qp[buf][rt] = qpart;
    }
}

// Full single-site step on C (rare slow-path commit). Two internal barriers.
__device__ __forceinline__ void site_full(Smem* __restrict__ sm, float C[6][6],
                                          int j, int rt, int ct, bool occupied)
{
    float p[6];
    produce_site(sm, C, p, j, 0, rt, ct);
    __syncthreads();
    const float* wp = &sm->w[0][6 * ct];
    float wc0 = wp[0], wc1 = wp[1], wc2 = wp[2], wc3 = wp[3], wc4 = wp[4], wc5 = wp[5];
    const float q = sum16(sm->qp[0]);
    float inv;
    if (!occupied) {
        const float piv = 1.0f - q;
        inv = (fabsf(piv) > 1e-30f) ? __frcp_rn(piv) : 0.0f;
    } else {
        inv = (fabsf(q) > 1e-30f) ? (-__frcp_rn(q)) : 0.0f;
    }
#pragma unroll
    for (int a = 0; a < 6; a++) {
        const float t = p[a] * inv;
        C[a][0] += t*wc0; C[a][1] += t*wc1; C[a][2] += t*wc2;
        C[a][3] += t*wc3; C[a][4] += t*wc4; C[a][5] += t*wc5;
    }
    __syncthreads();
}

__global__ void __launch_bounds__(TPB, 1)
sds_kernel(const float* __restrict__ eig, const float* __restrict__ u,
           float* __restrict__ out)
{
    extern __shared__ unsigned char smraw[];
    Smem* sm = reinterpret_cast<Smem*>(smraw);
    const int tid  = threadIdx.x;
    const int lane = tid & 31;
    const int warp = tid >> 5;
    const int rt   = tid >> 4;   // row-tile (rows 6rt..6rt+5)
    const int ct   = tid & 15;   // col-tile (cols 6ct..6ct+5)

    // Load P = eigfunc[:, :96] (first 96 entries of each 384-row).
    for (int idx = tid; idx < Dn * Nn; idx += TPB) {
        const int r = idx / Nn, c = idx - r * Nn;
        sm->P[idx] = eig[r * Dn + c];
    }

    // Committed conditional-kernel factor C (96x96) = I, 6x6 tile per thread.
    float cb[6][6];
#pragma unroll
    for (int a = 0; a < 6; a++)
#pragma unroll
        for (int b = 0; b < 6; b++)
            cb[a][b] = (6 * rt + a == 6 * ct + b) ? 1.0f : 0.0f;

    __syncthreads();

    int prev = -1;
    for (int k = 0; k < Nn; k++) {
        const int xmin = prev + 1;
        const int xmax = Dn - Nn + k + 1;   // exclusive
        const float uk = u[k];

        // Working copy for the speculative (all-empty) scan.
        float cw[6][6];
#pragma unroll
        for (int a = 0; a < 6; a++)
#pragma unroll
            for (int b = 0; b < 6; b++)
                cw[a][b] = cb[a][b];

        float run = 1.0f;    // prod of pivots (1-q), replicated
        float cdf = 0.0f;    // running cdf, replicated
        bool  strict = false;
        int   jstart = xmin;
        int   pos;

        for (;;) {  // scan (with possible strict-mode resume)
            int buf = 0;
            float p[6];
            produce_site(sm, cw, p, jstart, buf, rt, ct);
            int j = jstart;
            int jend;
            float ar_exit;
            for (;;) {
                __syncthreads();
                // ---- consume site j ----
                const float* wp = &sm->w[buf][6 * ct];
                const float wc0 = wp[0], wc1 = wp[1], wc2 = wp[2],
                            wc3 = wp[3], wc4 = wp[4], wc5 = wp[5];
                const float q = sum16(sm->qp[buf]);
                const float piv = 1.0f - q;
                const float inv = (fabsf(piv) > 1e-30f) ? __frcp_rn(piv) : 0.0f;

                const int hidx = j - xmin;
                if (hidx < WHIST) {
                    if (ct == 0) {
#pragma unroll
                        for (int a = 0; a < 6; a++)
                            sm->whist[hidx][6 * rt + a] = p[a];
                    }
                    if (tid == 0) { sm->invh[hidx] = inv; sm->qh[hidx] = q; }
                }

                // rank-1 update: C += (p*inv) (w_cols)^T
#pragma unroll
                for (int a = 0; a < 6; a++) {
                    const float t = p[a] * inv;
                    cw[a][0] += t*wc0; cw[a][1] += t*wc1; cw[a][2] += t*wc2;
                    cw[a][3] += t*wc3; cw[a][4] += t*wc4; cw[a][5] += t*wc5;
                }

                // replicated scalar bookkeeping (identical in all threads)
                float prob = run * q;
                if (!(fabsf(prob) > 1e-15f)) prob = 0.0f;
                cdf += prob;
                if (tid == 0) { sm->probs[j] = prob; sm->cdfa[j] = cdf; }
                run *= (1.0f - q);

                const int jn = j + 1;
                const float ar = fabsf(run);
                // Exit: strict tail rule, or verified-bracket rule (position is
                // re-checked with both bracket thresholds below; resume if
                // ambiguous, so this is not a correctness gamble).
                bool stop = (ar < 3e-9f * cdf);
                if (!strict)
                    stop = stop || ((uk * (cdf + ar) < cdf * (1.0f - 1e-4f)) &&
                                    (ar < 3e-4f * cdf));
                if (stop || jn >= xmax) { jend = jn; ar_exit = ar; break; }

                // ---- produce site jn on the just-updated C ----
                produce_site(sm, cw, p, jn, buf ^ 1, rt, ct);
                buf ^= 1;
                j = jn;
            }
            __syncthreads();   // probs/cdfa/whist visible

            // ---- position selection (bracketed thresholds) ----
            const bool fullwin = (jend >= xmax);
            const float thr_mid = uk * cdf;
            const float thr_lo  = thr_mid * (1.0f - 3e-6f);
            const float thr_hi  = uk * (cdf + ar_exit) * (1.0f + 3e-6f);
            const int len = jend - xmin;           // <= 289 (2 elems/thread)
            int packed = 0;
            if (tid < len) {
                const float cv = sm->cdfa[xmin + tid];
                packed += (cv < thr_lo ? 1 : 0)
                        + ((cv < thr_mid ? 1 : 0) << 10)
                        + ((cv < thr_hi ? 1 : 0) << 20);
            }
            if (tid + TPB < len) {
                const float cv = sm->cdfa[xmin + tid + TPB];
                packed += (cv < thr_lo ? 1 : 0)
                        + ((cv < thr_mid ? 1 : 0) << 10)
                        + ((cv < thr_hi ? 1 : 0) << 20);
            }
            const int wsum = __reduce_add_sync(FULLMASK, packed);
            if (lane == 0) sm->cnt[warp] = wsum;
            __syncthreads();
            int tot = 0;
#pragma unroll
            for (int i = 0; i < 8; i++) tot += sm->cnt[i];
            const int c_lo  = tot & 1023;
            const int c_mid = (tot >> 10) & 1023;
            const int c_hi  = (tot >> 20) & 1023;
            const int pmaxr = xmax - 1;
            int p_lo  = xmin + c_lo;  if (p_lo  > pmaxr) p_lo  = pmaxr;
            int p_mid = xmin + c_mid; if (p_mid > pmaxr) p_mid = pmaxr;
            int p_hi  = xmin + c_hi;  if (p_hi  > pmaxr) p_hi  = pmaxr;

            if (strict || fullwin) { pos = p_mid; break; }
            if (p_lo == p_hi)      { pos = p_lo;  break; }
            // Ambiguous: resume scanning in strict mode (state preserved).
            strict = true;
            jstart = jend;
        }

        // ---- commit onto cb: replay stored rank-1s (no barriers) ----
        const int m = pos - xmin;                 // site index of pos in window
        const int hlast = (m < WHIST) ? m : (WHIST - 1);
        for (int h = 0; h <= hlast; h++) {
            float iv;
            if (h == m) {
                const float qv = sm->qh[h];
                iv = (fabsf(qv) > 1e-30f) ? (-__frcp_rn(qv)) : 0.0f;
            } else {
                iv = sm->invh[h];
            }
            const float* wr = &sm->whist[h][6 * rt];
            const float* wc = &sm->whist[h][6 * ct];
            const float c0 = wc[0], c1 = wc[1], c2 = wc[2],
                        c3 = wc[3], c4 = wc[4], c5 = wc[5];
#pragma unroll
            for (int a = 0; a < 6; a++) {
                const float t = wr[a] * iv;
                cb[a][0] += t*c0; cb[a][1] += t*c1; cb[a][2] += t*c2;
                cb[a][3] += t*c3; cb[a][4] += t*c4; cb[a][5] += t*c5;
            }
        }
        if (m >= WHIST) {   // rare: replay the remainder at full price
            for (int j = xmin + WHIST; j <= pos; j++)
                site_full(sm, cb, j, rt, ct, j == pos);
        }

        if (tid == 0) {
            out[k]      = (float)pos;       // positions, then cond_probs
            out[Nn + k] = sm->probs[pos];
        }
        prev = pos;
        __syncthreads();   // whist reads done before next step rewrites it
    }
}

extern "C" void kernel_launch(void* const* d_in, const int* in_sizes, int n_in,
                              void* d_out, int out_size)
{
    (void)in_sizes; (void)n_in; (void)out_size;
    const float* eig = (const float*)d_in[0];   // eigfunc (384,384) f32
    const float* uu  = (const float*)d_in[1];   // u (96,) f32
    float* out = (float*)d_out;                 // [positions(96); cond_probs(96)]

    cudaFuncSetAttribute(sds_kernel,
                         cudaFuncAttributeMaxDynamicSharedMemorySize,
                         (int)sizeof(Smem));
    sds_kernel<<<1, TPB, sizeof(Smem)>>>(eig, uu, out);
}

// round 7
// speedup vs baseline: 4.2043x; 1.0579x over previous
#include <cuda_runtime.h>
#include <math.h>

#define Dn 384
#define Nn 96
#define TPB 256
#define WHIST 64
#define FULLMASK 0xffffffffu

// Dynamic shared memory (~178 KB).
struct Smem {
    float P[Dn * Nn];                 // eigfunc[:, :96] row-major [site][comp]
    float probs[Dn];                  // window probs
    float cdfa[Dn];                   // window running cdf
    __align__(16) float w[2][2 * Nn]; // [buf][ w1(96) | w2(96) ]
    __align__(16) float qpb[2][96];   // [buf][ q1p(32) | sp(32) | q2p(32) ]
    float whist[WHIST][Nn];           // per-site w history (cheap commit)
    float invh[WHIST];                // per-site empty-conditioning inverse
    float qh[WHIST];                  // per-site q
    int   cnt[8];                     // per-warp counts for selection
};

__device__ __forceinline__ void load12(const float* src, float d[12]) {
    const float4* s4 = reinterpret_cast<const float4*>(src);
    float4 a = s4[0], b = s4[1], c = s4[2];
    d[0]=a.x; d[1]=a.y; d[2]=a.z; d[3]=a.w;
    d[4]=b.x; d[5]=b.y; d[6]=b.z; d[7]=b.w;
    d[8]=c.x; d[9]=c.y; d[10]=c.z; d[11]=c.w;
}

// Deterministic fixed-order sum of 32 floats (16B-aligned smem).
__device__ __forceinline__ float sum32(const float* q) {
    const float4* q4 = reinterpret_cast<const float4*>(q);
    float t[8];
#pragma unroll
    for (int i = 0; i < 8; i++) {
        float4 v = q4[i];
        t[i] = (v.x + v.y) + (v.z + v.w);
    }
    return ((t[0]+t[1]) + (t[2]+t[3])) + ((t[4]+t[5]) + (t[6]+t[7]));
}

// Balanced 12-term dot (4 accumulators), fixed order.
__device__ __forceinline__ float dot12(const float* c, const float v[12]) {
    float a = c[0]*v[0]; a = fmaf(c[4], v[4], a); a = fmaf(c[8],  v[8],  a);
    float b = c[1]*v[1]; b = fmaf(c[5], v[5], b); b = fmaf(c[9],  v[9],  b);
    float d = c[2]*v[2]; d = fmaf(c[6], v[6], d); d = fmaf(c[10], v[10], d);
    float e = c[3]*v[3]; e = fmaf(c[7], v[7], e); e = fmaf(c[11], v[11], e);
    return (a + b) + (d + e);
}

// Tiling: 256 threads; rt = tid>>3 (rows 3rt..3rt+2, 32 groups),
//         ct = tid&7  (cols 12ct..12ct+11, 8 groups).
// Row-reduce: 3-level butterfly (offsets 1,2,4) within 8-lane subgroups.

// Produce one site j: p1 = full w rows for this thread's 3 rows; write w rows
// and the per-rowgroup q partial to buffer `buf`.
__device__ __forceinline__ void produce1(Smem* __restrict__ sm,
                                         const float C[3][12], float p1[3],
                                         int j, int buf, int rt, int ct)
{
    float v[12];
    load12(&sm->P[j * Nn + 12 * ct], v);
    p1[0] = dot12(C[0], v);
    p1[1] = dot12(C[1], v);
    p1[2] = dot12(C[2], v);
#pragma unroll
    for (int off = 1; off < 8; off <<= 1) {
        p1[0] += __shfl_xor_sync(FULLMASK, p1[0], off);
        p1[1] += __shfl_xor_sync(FULLMASK, p1[1], off);
        p1[2] += __shfl_xor_sync(FULLMASK, p1[2], off);
    }
    const float* vr = &sm->P[j * Nn + 3 * rt];
    const float qp = vr[0]*p1[0] + vr[1]*p1[1] + vr[2]*p1[2];
    if (ct == 0) {
        sm->w[buf][3*rt+0] = p1[0];
        sm->w[buf][3*rt+1] = p1[1];
        sm->w[buf][3*rt+2] = p1[2];
        sm->qpb[buf][rt] = qp;
    }
}

// Produce a pair (j, j+1) against the SAME C: p1 = C v_j, p2 = C v_{j+1},
// q partials q1p = v_j.p1, sp = v_{j+1}.p1, q2p = v_{j+1}.p2.
__device__ __forceinline__ void produce2(Smem* __restrict__ sm,
                                         const float C[3][12],
                                         float p1[3], float p2[3],
                                         int j, int buf, int rt, int ct)
{
    float v1[12], v2[12];
    load12(&sm->P[j * Nn + 12 * ct], v1);
    load12(&sm->P[(j + 1) * Nn + 12 * ct], v2);
#pragma unroll
    for (int a = 0; a < 3; a++) {
        p1[a] = dot12(C[a], v1);
        p2[a] = dot12(C[a], v2);
    }
#pragma unroll
    for (int off = 1; off < 8; off <<= 1) {
        p1[0] += __shfl_xor_sync(FULLMASK, p1[0], off);
        p1[1] += __shfl_xor_sync(FULLMASK, p1[1], off);
        p1[2] += __shfl_xor_sync(FULLMASK, p1[2], off);
        p2[0] += __shfl_xor_sync(FULLMASK, p2[0], off);
        p2[1] += __shfl_xor_sync(FULLMASK, p2[1], off);
        p2[2] += __shfl_xor_sync(FULLMASK, p2[2], off);
    }
    const float* vr1 = &sm->P[j * Nn + 3 * rt];
    const float* vr2 = &sm->P[(j + 1) * Nn + 3 * rt];
    const float q1p = vr1[0]*p1[0] + vr1[1]*p1[1] + vr1[2]*p1[2];
    const float sp  = vr2[0]*p1[0] + vr2[1]*p1[1] + vr2[2]*p1[2];
    const float q2p = vr2[0]*p2[0] + vr2[1]*p2[1] + vr2[2]*p2[2];
    if (ct == 0) {
        sm->w[buf][3*rt+0]      = p1[0];
        sm->w[buf][3*rt+1]      = p1[1];
        sm->w[buf][3*rt+2]      = p1[2];
        sm->w[buf][Nn+3*rt+0]   = p2[0];
        sm->w[buf][Nn+3*rt+1]   = p2[1];
        sm->w[buf][Nn+3*rt+2]   = p2[2];
        sm->qpb[buf][rt]        = q1p;
        sm->qpb[buf][32 + rt]   = sp;
        sm->qpb[buf][64 + rt]   = q2p;
    }
}

// Full single-site step on C (rare slow-path commit tail). Two internal bars.
__device__ __forceinline__ void site_full(Smem* __restrict__ sm, float C[3][12],
                                          int j, int rt, int ct, bool occupied)
{
    float p[3];
    produce1(sm, C, p, j, 0, rt, ct);
    __syncthreads();
    float wc[12];
    load12(&sm->w[0][12 * ct], wc);
    const float q = sum32(&sm->qpb[0][0]);
    float inv;
    if (!occupied) {
        const float piv = 1.0f - q;
        inv = (fabsf(piv) > 1e-30f) ? __frcp_rn(piv) : 0.0f;
    } else {
        inv = (fabsf(q) > 1e-30f) ? (-__frcp_rn(q)) : 0.0f;
    }
#pragma unroll
    for (int a = 0; a < 3; a++) {
        const float t = p[a] * inv;
#pragma unroll
        for (int b = 0; b < 12; b++) C[a][b] += t * wc[b];
    }
    __syncthreads();
}

__global__ void __launch_bounds__(TPB, 1)
sds_kernel(const float* __restrict__ eig, const float* __restrict__ u,
           float* __restrict__ out)
{
    extern __shared__ unsigned char smraw[];
    Smem* sm = reinterpret_cast<Smem*>(smraw);
    const int tid  = threadIdx.x;
    const int lane = tid & 31;
    const int warp = tid >> 5;
    const int rt   = tid >> 3;   // row-tile (rows 3rt..3rt+2)
    const int ct   = tid & 7;    // col-tile (cols 12ct..12ct+11)

    // Load P = eigfunc[:, :96] (first 96 entries of each 384-row).
    for (int idx = tid; idx < Dn * Nn; idx += TPB) {
        const int r = idx / Nn, c = idx - r * Nn;
        sm->P[idx] = eig[r * Dn + c];
    }

    // Committed conditional-kernel factor C (96x96) = I, 3x12 tile/thread.
    float cb[3][12];
#pragma unroll
    for (int a = 0; a < 3; a++)
#pragma unroll
        for (int b = 0; b < 12; b++)
            cb[a][b] = (3 * rt + a == 12 * ct + b) ? 1.0f : 0.0f;

    __syncthreads();

    int prev = -1;
    for (int k = 0; k < Nn; k++) {
        const int xmin = prev + 1;
        const int xmax = Dn - Nn + k + 1;   // exclusive
        const float uk = u[k];

        // Working copy for the speculative (all-empty) scan.
        float cw[3][12];
#pragma unroll
        for (int a = 0; a < 3; a++)
#pragma unroll
            for (int b = 0; b < 12; b++)
                cw[a][b] = cb[a][b];

        float run = 1.0f;    // prod of pivots (1-q), replicated
        float cdf = 0.0f;    // running cdf, replicated
        bool  strict = false;
        int   jstart = xmin;
        int   pos;

        for (;;) {  // scan (with possible strict-mode resume)
            int buf = 0;
            int j = jstart;
            int nb = (xmax - j >= 2) ? 2 : 1;
            float p1[3], p2[3];
            if (nb == 2) produce2(sm, cw, p1, p2, j, buf, rt, ct);
            else         produce1(sm, cw, p1, j, buf, rt, ct);
            int jend;
            float ar_exit;
            for (;;) {
                __syncthreads();
                if (nb == 2) {
                    // ---- consume pair (j, j+1) ----
                    float wc1[12], wc2[12];
                    load12(&sm->w[buf][12 * ct], wc1);
                    load12(&sm->w[buf][Nn + 12 * ct], wc2);
                    const float q1  = sum32(&sm->qpb[buf][0]);
                    const float s   = sum32(&sm->qpb[buf][32]);
                    const float q2r = sum32(&sm->qpb[buf][64]);
                    const float piv1 = 1.0f - q1;
                    const float inv1 = (fabsf(piv1) > 1e-30f) ? __frcp_rn(piv1) : 0.0f;
                    const float t = inv1 * s;
                    const float q2 = q2r + t * s;     // v2^T C' v2 (Schur)
                    const float piv2 = 1.0f - q2;
                    const float inv2 = (fabsf(piv2) > 1e-30f) ? __frcp_rn(piv2) : 0.0f;
                    float p2c[3], wc2c[12];
#pragma unroll
                    for (int a = 0; a < 3; a++) p2c[a] = p2[a] + t * p1[a];
#pragma unroll
                    for (int b = 0; b < 12; b++) wc2c[b] = wc2[b] + t * wc1[b];

                    const int h1 = j - xmin;
                    if (ct == 0) {
                        if (h1 < WHIST) {
#pragma unroll
                            for (int a = 0; a < 3; a++)
                                sm->whist[h1][3*rt+a] = p1[a];
                        }
                        if (h1 + 1 < WHIST) {
#pragma unroll
                            for (int a = 0; a < 3; a++)
                                sm->whist[h1+1][3*rt+a] = p2c[a];
                        }
                    }
                    if (tid == 0) {
                        if (h1 < WHIST)     { sm->invh[h1]   = inv1; sm->qh[h1]   = q1; }
                        if (h1 + 1 < WHIST) { sm->invh[h1+1] = inv2; sm->qh[h1+1] = q2; }
                    }
                    // rank-2 update
#pragma unroll
                    for (int a = 0; a < 3; a++) {
                        const float u1 = p1[a]  * inv1;
                        const float u2 = p2c[a] * inv2;
#pragma unroll
                        for (int b = 0; b < 12; b++) {
                            cw[a][b] += u1 * wc1[b];
                            cw[a][b] += u2 * wc2c[b];
                        }
                    }
                    // replicated bookkeeping (identical in all threads)
                    float prob = run * q1;
                    if (!(fabsf(prob) > 1e-15f)) prob = 0.0f;
                    cdf += prob;
                    if (tid == 0) { sm->probs[j] = prob; sm->cdfa[j] = cdf; }
                    run *= (1.0f - q1);
                    prob = run * q2;
                    if (!(fabsf(prob) > 1e-15f)) prob = 0.0f;
                    cdf += prob;
                    if (tid == 0) { sm->probs[j+1] = prob; sm->cdfa[j+1] = cdf; }
                    run *= (1.0f - q2);
                } else {
                    // ---- consume single site j ----
                    float wc1[12];
                    load12(&sm->w[buf][12 * ct], wc1);
                    const float q1 = sum32(&sm->qpb[buf][0]);
                    const float piv1 = 1.0f - q1;
                    const float inv1 = (fabsf(piv1) > 1e-30f) ? __frcp_rn(piv1) : 0.0f;
                    const int h1 = j - xmin;
                    if (ct == 0 && h1 < WHIST) {
#pragma unroll
                        for (int a = 0; a < 3; a++)
                            sm->whist[h1][3*rt+a] = p1[a];
                    }
                    if (tid == 0 && h1 < WHIST) {
                        sm->invh[h1] = inv1; sm->qh[h1] = q1;
                    }
#pragma unroll
                    for (int a = 0; a < 3; a++) {
                        const float t = p1[a] * inv1;
#pragma unroll
                        for (int b = 0; b < 12; b++) cw[a][b] += t * wc1[b];
                    }
                    float prob = run * q1;
                    if (!(fabsf(prob) > 1e-15f)) prob = 0.0f;
                    cdf += prob;
                    if (tid == 0) { sm->probs[j] = prob; sm->cdfa[j] = cdf; }
                    run *= (1.0f - q1);
                }

                const int jn = j + nb;
                const float ar = fabsf(run);
                // Exit: strict tail rule, or verified-bracket rule (position
                // re-checked with both bracket thresholds; resume if ambiguous).
                bool stop = (ar < 3e-9f * cdf);
                if (!strict)
                    stop = stop || ((uk * (cdf + ar) < cdf * (1.0f - 1e-4f)) &&
                                    (ar < 3e-4f * cdf));
                if (stop || jn >= xmax) { jend = jn; ar_exit = ar; break; }

                const int nb2 = (xmax - jn >= 2) ? 2 : 1;
                if (nb2 == 2) produce2(sm, cw, p1, p2, jn, buf ^ 1, rt, ct);
                else          produce1(sm, cw, p1, jn, buf ^ 1, rt, ct);
                buf ^= 1; j = jn; nb = nb2;
            }
            __syncthreads();   // probs/cdfa/whist visible

            // ---- position selection (bracketed thresholds) ----
            const bool fullwin = (jend >= xmax);
            const float thr_mid = uk * cdf;
            const float thr_lo  = thr_mid * (1.0f - 3e-6f);
            const float thr_hi  = uk * (cdf + ar_exit) * (1.0f + 3e-6f);
            const int len = jend - xmin;           // <= 289 (2 elems/thread)
            int packed = 0;
            if (tid < len) {
                const float cv = sm->cdfa[xmin + tid];
                packed += (cv < thr_lo ? 1 : 0)
                        + ((cv < thr_mid ? 1 : 0) << 10)
                        + ((cv < thr_hi ? 1 : 0) << 20);
            }
            if (tid + TPB < len) {
                const float cv = sm->cdfa[xmin + tid + TPB];
                packed += (cv < thr_lo ? 1 : 0)
                        + ((cv < thr_mid ? 1 : 0) << 10)
                        + ((cv < thr_hi ? 1 : 0) << 20);
            }
            const int wsum = __reduce_add_sync(FULLMASK, packed);
            if (lane == 0) sm->cnt[warp] = wsum;
            __syncthreads();
            int tot = 0;
#pragma unroll
            for (int i = 0; i < 8; i++) tot += sm->cnt[i];
            const int c_lo  = tot & 1023;
            const int c_mid = (tot >> 10) & 1023;
            const int c_hi  = (tot >> 20) & 1023;
            const int pmaxr = xmax - 1;
            int p_lo  = xmin + c_lo;  if (p_lo  > pmaxr) p_lo  = pmaxr;
            int p_mid = xmin + c_mid; if (p_mid > pmaxr) p_mid = pmaxr;
            int p_hi  = xmin + c_hi;  if (p_hi  > pmaxr) p_hi  = pmaxr;

            if (strict || fullwin) { pos = p_mid; break; }
            if (p_lo == p_hi)      { pos = p_lo;  break; }
            strict = true;
            jstart = jend;
        }

        // ---- commit onto cb: replay stored rank-1s (no barriers) ----
        const int m = pos - xmin;
        const int hlast = (m < WHIST) ? m : (WHIST - 1);
        for (int h = 0; h <= hlast; h++) {
            float iv;
            if (h == m) {
                const float qv = sm->qh[h];
                iv = (fabsf(qv) > 1e-30f) ? (-__frcp_rn(qv)) : 0.0f;
            } else {
                iv = sm->invh[h];
            }
            const float* wr = &sm->whist[h][3 * rt];
            float wc[12];
            load12(&sm->whist[h][12 * ct], wc);
#pragma unroll
            for (int a = 0; a < 3; a++) {
                const float t = wr[a] * iv;
#pragma unroll
                for (int b = 0; b < 12; b++) cb[a][b] += t * wc[b];
            }
        }
        if (m >= WHIST) {   // rare: replay the remainder at full price
            for (int j = xmin + WHIST; j <= pos; j++)
                site_full(sm, cb, j, rt, ct, j == pos);
        }

        if (tid == 0) {
            out[k]      = (float)pos;       // positions, then cond_probs
            out[Nn + k] = sm->probs[pos];
        }
        prev = pos;
        __syncthreads();   // whist reads done before next step rewrites it
    }
}

extern "C" void kernel_launch(void* const* d_in, const int* in_sizes, int n_in,
                              void* d_out, int out_size)
{
    (void)in_sizes; (void)n_in; (void)out_size;
    const float* eig = (const float*)d_in[0];   // eigfunc (384,384) f32
    const float* uu  = (const float*)d_in[1];   // u (96,) f32
    float* out = (float*)d_out;                 // [positions(96); cond_probs(96)]

    cudaFuncSetAttribute(sds_kernel,
                         cudaFuncAttributeMaxDynamicSharedMemorySize,
                         (int)sizeof(Smem));
    sds_kernel<<<1, TPB, sizeof(Smem)>>>(eig, uu, out);
}